// round 7
// baseline (speedup 1.0000x reference)
#include <cuda_runtime.h>
#include <math.h>

#define B_  8
#define C_  3
#define H_  512
#define W_  512
#define FR_ 3
#define KS_ 7

#define TW   32                 // tile width (pixels)
#define TH   16                 // tile height (pixels)
#define HALY (TH + 2*FR_)       // 22 rows
#define HALX (TW + 2*FR_)       // 38 floats wide
#define P2   21                 // row pitch in u64 units (42 floats)
#define NT   256
#define NBLOCKS (B_ * (H_/TH) * (W_/TW))   // 8*32*16 = 4096

typedef unsigned long long u64;

__device__ float        g_partials[NBLOCKS];
__device__ unsigned int g_done = 0;   // self-resetting via atomicInc wrap

// ---- f32x2 packed helpers (sm_103a) ----
__device__ __forceinline__ void upk2(u64 v, float& a, float& b) {
    asm("mov.b64 {%0,%1}, %2;" : "=f"(a), "=f"(b) : "l"(v));
}
__device__ __forceinline__ u64 mul2(u64 a, u64 b) {
    u64 r; asm("mul.rn.f32x2 %0,%1,%2;" : "=l"(r) : "l"(a), "l"(b)); return r;
}
__device__ __forceinline__ u64 add2(u64 a, u64 b) {
    u64 r; asm("add.rn.f32x2 %0,%1,%2;" : "=l"(r) : "l"(a), "l"(b)); return r;
}
__device__ __forceinline__ u64 fma2(u64 a, u64 b, u64 c) {
    u64 r; asm("fma.rn.f32x2 %0,%1,%2,%3;" : "=l"(r) : "l"(a), "l"(b), "l"(c)); return r;
}
__device__ __forceinline__ u64 abs2(u64 a) { return a & 0x7FFFFFFF7FFFFFFFull; }
__device__ __forceinline__ u64 ex2_2(u64 x) {
    u64 r;
    asm("{.reg .b32 lo,hi;\n\t"
        "mov.b64 {lo,hi}, %1;\n\t"
        "ex2.approx.ftz.f32 lo, lo;\n\t"
        "ex2.approx.ftz.f32 hi, hi;\n\t"
        "mov.b64 %0, {lo,hi};}" : "=l"(r) : "l"(x));
    return r;
}
__device__ __forceinline__ u64 bc2(float x) {   // compile-time broadcast
    unsigned int u = __float_as_uint(x);
    return ((u64)u << 32) | (u64)u;
}

__device__ __forceinline__ int reflect_idx(int i, int n) {
    if (i < 0) i = -i;
    if (i >= n) i = 2*n - 2 - i;
    return i;
}

__global__ __launch_bounds__(NT, 5)
void blt_loss_kernel(const float* __restrict__ in, float* __restrict__ out)
{
    // tA: tile; tB: tile shifted left one float. All tap pairs -> aligned LDS.64.
    __shared__ u64 tA[C_][HALY][P2];
    __shared__ u64 tB[C_][HALY][P2];
    __shared__ float warp_sums[NT / 32];
    __shared__ int   is_last;

    const int tid = threadIdx.x;
    const int x0b = blockIdx.x * TW;
    const int y0b = blockIdx.y * TH;
    const int b   = blockIdx.z;

    // ---- load tile + halo (reflect), write both copies ----
    {
        float* fA = (float*)tA;
        float* fB = (float*)tB;
        const float* base = in + (size_t)b * C_ * H_ * W_;
        for (int idx = tid; idx < C_ * HALY * HALX; idx += NT) {
            int c   = idx / (HALY * HALX);
            int rem = idx - c * (HALY * HALX);
            int iy  = rem / HALX;
            int ix  = rem - iy * HALX;
            int gy  = reflect_idx(y0b - FR_ + iy, H_);
            int gx  = reflect_idx(x0b - FR_ + ix, W_);
            float v = base[(c * H_ + gy) * W_ + gx];
            int off = (c * HALY + iy) * (2 * P2);
            fA[off + ix] = v;
            if (ix > 0) fB[off + ix - 1] = v;
        }
    }
    __syncthreads();

    // Thread -> one packed pair of pixels: tile cols (2h, 2h+1)
    const int ty = tid >> 4;            // 0..15
    const int h  = tid & 15;            // 0..15 (u64 index)

    const u64 c0 = tB[0][ty + FR_][h + 1];   // pixel cols 2h+3, 2h+4
    const u64 c1 = tB[1][ty + FR_][h + 1];
    const u64 c2 = tB[2][ty + FR_][h + 1];

    const float LOG2A = -2.65056562f;
    const float LGK[4] = { 0.0f, -0.72134751f, -2.88539004f, -6.49212760f };
    const u64 SC2  = bc2(-72.13475204f);   // -50*log2(e)
    const u64 NEG1 = bc2(-1.0f);

    u64 acc0 = 0, acc1 = 0;

    #pragma unroll
    for (int k = 0; k < KS_; k++) {
        const int   row = ty + k;
        const float lgk = LGK[(k < FR_) ? (FR_ - k) : (k - FR_)];

        #pragma unroll
        for (int l = 0; l < KS_; l++) {
            if (k == FR_ && l == FR_) continue;   // center tap contributes 0

            const float lc  = LOG2A + lgk + LGK[(l < FR_) ? (FR_ - l) : (l - FR_)];
            const u64   lc2 = bc2(lc);
            const int   j   = l >> 1;

            // neighbor pair at cols (2h+l, 2h+l+1): parity picks the copy
            u64 n0 = (l & 1) ? tB[0][row][h + j] : tA[0][row][h + j];
            u64 n1 = (l & 1) ? tB[1][row][h + j] : tA[1][row][h + j];
            u64 n2 = (l & 1) ? tB[2][row][h + j] : tA[2][row][h + j];

            u64 d0 = fma2(n0, NEG1, c0);
            u64 d1 = fma2(n1, NEG1, c1);
            u64 d2 = fma2(n2, NEG1, c2);
            u64 s  = fma2(d2, d2, fma2(d1, d1, mul2(d0, d0)));
            u64 e  = ex2_2(fma2(s, SC2, lc2));
            u64 L  = add2(abs2(d0), add2(abs2(d1), abs2(d2)));
            if (l & 1) acc1 = fma2(L, e, acc1);
            else       acc0 = fma2(L, e, acc0);
        }
    }

    // ---- reduce: thread -> warp -> block ----
    u64 accP = add2(acc0, acc1);
    float a0, a1; upk2(accP, a0, a1);
    float acc = a0 + a1;

    #pragma unroll
    for (int ofs = 16; ofs > 0; ofs >>= 1)
        acc += __shfl_down_sync(0xffffffffu, acc, ofs);

    if ((tid & 31) == 0) warp_sums[tid >> 5] = acc;
    __syncthreads();

    if (tid == 0) {
        float bs = 0.0f;
        #pragma unroll
        for (int wi = 0; wi < NT / 32; wi++) bs += warp_sums[wi];
        const int bidx = (blockIdx.z * gridDim.y + blockIdx.y) * gridDim.x + blockIdx.x;
        g_partials[bidx] = bs;
        __threadfence();
        unsigned int old = atomicInc(&g_done, NBLOCKS - 1);  // wraps to 0: self-reset
        is_last = (old == NBLOCKS - 1);
    }
    __syncthreads();

    // ---- last block: final deterministic reduce ----
    if (is_last) {
        float s = 0.0f;
        for (int i = tid; i < NBLOCKS; i += NT)
            s += __ldcg(&g_partials[i]);

        #pragma unroll
        for (int ofs = 16; ofs > 0; ofs >>= 1)
            s += __shfl_down_sync(0xffffffffu, s, ofs);

        if ((tid & 31) == 0) warp_sums[tid >> 5] = s;
        __syncthreads();

        if (tid == 0) {
            float total = 0.0f;
            #pragma unroll
            for (int wi = 0; wi < NT / 32; wi++) total += warp_sums[wi];
            out[0] = total * (1.0f / (float)((size_t)B_ * C_ * H_ * W_));
        }
    }
}

extern "C" void kernel_launch(void* const* d_in, const int* in_sizes, int n_in,
                              void* d_out, int out_size)
{
    const float* in = (const float*)d_in[0];
    float* out = (float*)d_out;

    dim3 grid(W_ / TW, H_ / TH, B_);   // 16, 32, 8
    blt_loss_kernel<<<grid, NT>>>(in, out);
}

// round 8
// speedup vs baseline: 1.1894x; 1.1894x over previous
#include <cuda_runtime.h>
#include <math.h>

#define B_  8
#define C_  3
#define H_  512
#define W_  512
#define FR_ 3
#define KS_ 7

#define TILE 32
#define HALO (TILE + 2*FR_)     // 38
#define P2   21                 // row pitch in u64 units (42 floats): conflict-free
#define NT   256
#define NBLOCKS (B_ * (H_/TILE) * (W_/TILE))   // 2048

typedef unsigned long long u64;

__device__ float        g_partials[NBLOCKS];
__device__ unsigned int g_done = 0;   // self-resetting via atomicInc wrap

// ---- f32x2 packed helpers (sm_103a) ----
__device__ __forceinline__ u64 pk2(float a, float b) {
    u64 r; asm("mov.b64 %0, {%1,%2};" : "=l"(r) : "f"(a), "f"(b)); return r;
}
__device__ __forceinline__ void upk2(u64 v, float& a, float& b) {
    asm("mov.b64 {%0,%1}, %2;" : "=f"(a), "=f"(b) : "l"(v));
}
__device__ __forceinline__ u64 mul2(u64 a, u64 b) {
    u64 r; asm("mul.rn.f32x2 %0,%1,%2;" : "=l"(r) : "l"(a), "l"(b)); return r;
}
__device__ __forceinline__ u64 add2(u64 a, u64 b) {
    u64 r; asm("add.rn.f32x2 %0,%1,%2;" : "=l"(r) : "l"(a), "l"(b)); return r;
}
__device__ __forceinline__ u64 fma2(u64 a, u64 b, u64 c) {
    u64 r; asm("fma.rn.f32x2 %0,%1,%2,%3;" : "=l"(r) : "l"(a), "l"(b), "l"(c)); return r;
}
__device__ __forceinline__ u64 abs2(u64 a) { return a & 0x7FFFFFFF7FFFFFFFull; }
__device__ __forceinline__ u64 ex2_2(u64 x) {
    u64 r;
    asm("{.reg .b32 lo,hi;\n\t"
        "mov.b64 {lo,hi}, %1;\n\t"
        "ex2.approx.ftz.f32 lo, lo;\n\t"
        "ex2.approx.ftz.f32 hi, hi;\n\t"
        "mov.b64 %0, {lo,hi};}" : "=l"(r) : "l"(x));
    return r;
}
__device__ __forceinline__ u64 bc2(float x) {   // compile-time broadcast
    unsigned int u = __float_as_uint(x);
    return ((u64)u << 32) | (u64)u;
}

__device__ __forceinline__ int reflect_idx(int i, int n) {
    if (i < 0) i = -i;
    if (i >= n) i = 2*n - 2 - i;
    return i;
}

#define LOG2A  (-2.65056562f)       // log2(1/sumG^2)
#define GLOG   (-0.72134751f)       // log2(exp(-d^2/2)) coefficient: -d^2 * 0.72134751

__global__ __launch_bounds__(NT, 4)
void blt_loss_kernel(const float* __restrict__ in, float* __restrict__ out)
{
    // tA: tile; tB: tile shifted left one float. All tap pairs -> aligned LDS.64.
    __shared__ u64 tA[C_][HALO][P2];
    __shared__ u64 tB[C_][HALO][P2];
    __shared__ float warp_sums[NT / 32];
    __shared__ int   is_last;

    const int tid = threadIdx.x;
    const int x0b = blockIdx.x * TILE;
    const int y0b = blockIdx.y * TILE;
    const int b   = blockIdx.z;

    // ---- load tile + halo (reflect), write both copies ----
    {
        float* fA = (float*)tA;
        float* fB = (float*)tB;
        const float* base = in + (size_t)b * C_ * H_ * W_;
        for (int idx = tid; idx < C_ * HALO * HALO; idx += NT) {
            int c   = idx / (HALO * HALO);
            int rem = idx - c * (HALO * HALO);
            int iy  = rem / HALO;
            int ix  = rem - iy * HALO;
            int gy  = reflect_idx(y0b - FR_ + iy, H_);
            int gx  = reflect_idx(x0b - FR_ + ix, W_);
            float v = base[(c * H_ + gy) * W_ + gx];
            int off = (c * HALO + iy) * (2 * P2);
            fA[off + ix] = v;
            if (ix > 0) fB[off + ix - 1] = v;
        }
    }
    __syncthreads();

    // Thread -> 4 consecutive x pixels in one row (2 packed pairs)
    const int ty = tid >> 3;            // 0..31
    const int h  = (tid & 7) * 2;       // u64 base index; pair A px = x0b+2h..+1

    const u64 cA0 = tB[0][ty + FR_][h + 1];
    const u64 cA1 = tB[1][ty + FR_][h + 1];
    const u64 cA2 = tB[2][ty + FR_][h + 1];
    const u64 cB0 = tB[0][ty + FR_][h + 2];
    const u64 cB1 = tB[1][ty + FR_][h + 2];
    const u64 cB2 = tB[2][ty + FR_][h + 2];

    const u64 SC2  = bc2(-72.13475204f);   // -50*log2(e)
    const u64 NEG1 = bc2(-1.0f);

    u64 accA0 = 0, accA1 = 0, accB0 = 0, accB1 = 0;

    // ===== MAIN: 24 positive-half taps, weight 2 folded into lc (+1.0 in log2) =====
    #pragma unroll
    for (int k = FR_; k < KS_; k++) {          // dy = k-3 in 0..3
        const int row = ty + k;
        const int dy  = k - FR_;
        const int l0  = (k == FR_) ? (FR_ + 1) : 0;   // dy=0 -> dx>0 only

        #pragma unroll
        for (int l = 0; l < KS_; l++) {
            if (l < l0) continue;
            const int dx = l - FR_;
            const float lc  = LOG2A + 1.0f + GLOG * (float)(dy*dy + dx*dx);
            const u64   lc2 = bc2(lc);
            const int   j   = l >> 1;

            u64 nA0 = (l & 1) ? tB[0][row][h + j] : tA[0][row][h + j];
            u64 nA1 = (l & 1) ? tB[1][row][h + j] : tA[1][row][h + j];
            u64 nA2 = (l & 1) ? tB[2][row][h + j] : tA[2][row][h + j];
            u64 nB0 = (l & 1) ? tB[0][row][h + j + 1] : tA[0][row][h + j + 1];
            u64 nB1 = (l & 1) ? tB[1][row][h + j + 1] : tA[1][row][h + j + 1];
            u64 nB2 = (l & 1) ? tB[2][row][h + j + 1] : tA[2][row][h + j + 1];

            { // pair A
                u64 d0 = fma2(nA0, NEG1, cA0);
                u64 d1 = fma2(nA1, NEG1, cA1);
                u64 d2 = fma2(nA2, NEG1, cA2);
                u64 s  = fma2(d2, d2, fma2(d1, d1, mul2(d0, d0)));
                u64 e  = ex2_2(fma2(s, SC2, lc2));
                u64 L  = add2(abs2(d0), add2(abs2(d1), abs2(d2)));
                if (l & 1) accA1 = fma2(L, e, accA1);
                else       accA0 = fma2(L, e, accA0);
            }
            { // pair B
                u64 d0 = fma2(nB0, NEG1, cB0);
                u64 d1 = fma2(nB1, NEG1, cB1);
                u64 d2 = fma2(nB2, NEG1, cB2);
                u64 s  = fma2(d2, d2, fma2(d1, d1, mul2(d0, d0)));
                u64 e  = ex2_2(fma2(s, SC2, lc2));
                u64 L  = add2(abs2(d0), add2(abs2(d1), abs2(d2)));
                if (l & 1) accB1 = fma2(L, e, accB1);
                else       accB0 = fma2(L, e, accB0);
            }
        }
    }

    // ===== CORRECTION: only border blocks; exact fix for reflecting taps =====
    // For o in H reflecting: main counted 2x, want 1x -> subtract 1x.
    // For o not in H reflecting: main counted 0x, want 1x -> add 1x.
    if (x0b == 0 || y0b == 0 || x0b == W_ - TILE || y0b == H_ - TILE) {
        const int ys = y0b + ty;
        const int xa = x0b + 2 * h;     // pixels: xa..xa+3 (A: xa,xa+1; B: xa+2,xa+3)

        #pragma unroll 1
        for (int dy = -FR_; dy <= FR_; dy++) {
            const int  row  = ty + FR_ + dy;
            const bool inY  = (unsigned)(ys + dy) < (unsigned)H_;
            #pragma unroll 1
            for (int dx = -FR_; dx <= FR_; dx++) {
                if (dy == 0 && dx == 0) continue;
                const bool in0 = inY && ((unsigned)(xa + dx)     < (unsigned)W_);
                const bool in1 = inY && ((unsigned)(xa + 1 + dx) < (unsigned)W_);
                const bool in2 = inY && ((unsigned)(xa + 2 + dx) < (unsigned)W_);
                const bool in3 = inY && ((unsigned)(xa + 3 + dx) < (unsigned)W_);
                if (in0 & in1 & in2 & in3) continue;   // nothing reflects here

                const bool inH = (dy > 0) || (dy == 0 && dx > 0);
                const float sg = inH ? -1.0f : 1.0f;
                const u64 mA2 = pk2(in0 ? 0.0f : sg, in1 ? 0.0f : sg);
                const u64 mB2 = pk2(in2 ? 0.0f : sg, in3 ? 0.0f : sg);

                const float lc  = LOG2A + GLOG * (float)(dy*dy + dx*dx);  // 1x weight
                const u64   lc2 = pk2(lc, lc);

                const int l = dx + FR_;
                const int j = l >> 1;
                u64 nA0, nA1, nA2, nB0, nB1, nB2;
                if (l & 1) {
                    nA0 = tB[0][row][h+j];   nA1 = tB[1][row][h+j];   nA2 = tB[2][row][h+j];
                    nB0 = tB[0][row][h+j+1]; nB1 = tB[1][row][h+j+1]; nB2 = tB[2][row][h+j+1];
                } else {
                    nA0 = tA[0][row][h+j];   nA1 = tA[1][row][h+j];   nA2 = tA[2][row][h+j];
                    nB0 = tA[0][row][h+j+1]; nB1 = tA[1][row][h+j+1]; nB2 = tA[2][row][h+j+1];
                }

                { // pair A
                    u64 d0 = fma2(nA0, NEG1, cA0);
                    u64 d1 = fma2(nA1, NEG1, cA1);
                    u64 d2 = fma2(nA2, NEG1, cA2);
                    u64 s  = fma2(d2, d2, fma2(d1, d1, mul2(d0, d0)));
                    u64 e  = ex2_2(fma2(s, SC2, lc2));
                    u64 L  = add2(abs2(d0), add2(abs2(d1), abs2(d2)));
                    accA0  = fma2(mul2(L, mA2), e, accA0);
                }
                { // pair B
                    u64 d0 = fma2(nB0, NEG1, cB0);
                    u64 d1 = fma2(nB1, NEG1, cB1);
                    u64 d2 = fma2(nB2, NEG1, cB2);
                    u64 s  = fma2(d2, d2, fma2(d1, d1, mul2(d0, d0)));
                    u64 e  = ex2_2(fma2(s, SC2, lc2));
                    u64 L  = add2(abs2(d0), add2(abs2(d1), abs2(d2)));
                    accB0  = fma2(mul2(L, mB2), e, accB0);
                }
            }
        }
    }

    // ---- reduce: thread -> warp -> block ----
    u64 accP = add2(add2(accA0, accA1), add2(accB0, accB1));
    float a0, a1; upk2(accP, a0, a1);
    float acc = a0 + a1;

    #pragma unroll
    for (int ofs = 16; ofs > 0; ofs >>= 1)
        acc += __shfl_down_sync(0xffffffffu, acc, ofs);

    if ((tid & 31) == 0) warp_sums[tid >> 5] = acc;
    __syncthreads();

    if (tid == 0) {
        float bs = 0.0f;
        #pragma unroll
        for (int wi = 0; wi < NT / 32; wi++) bs += warp_sums[wi];
        const int bidx = (blockIdx.z * gridDim.y + blockIdx.y) * gridDim.x + blockIdx.x;
        g_partials[bidx] = bs;
        __threadfence();
        unsigned int old = atomicInc(&g_done, NBLOCKS - 1);  // wraps to 0: self-reset
        is_last = (old == NBLOCKS - 1);
    }
    __syncthreads();

    // ---- last block: final deterministic reduce ----
    if (is_last) {
        float s = 0.0f;
        for (int i = tid; i < NBLOCKS; i += NT)
            s += __ldcg(&g_partials[i]);

        #pragma unroll
        for (int ofs = 16; ofs > 0; ofs >>= 1)
            s += __shfl_down_sync(0xffffffffu, s, ofs);

        if ((tid & 31) == 0) warp_sums[tid >> 5] = s;
        __syncthreads();

        if (tid == 0) {
            float total = 0.0f;
            #pragma unroll
            for (int wi = 0; wi < NT / 32; wi++) total += warp_sums[wi];
            out[0] = total * (1.0f / (float)((size_t)B_ * C_ * H_ * W_));
        }
    }
}

extern "C" void kernel_launch(void* const* d_in, const int* in_sizes, int n_in,
                              void* d_out, int out_size)
{
    const float* in = (const float*)d_in[0];
    float* out = (float*)d_out;

    dim3 grid(W_ / TILE, H_ / TILE, B_);   // 16,16,8
    blt_loss_kernel<<<grid, NT>>>(in, out);
}

// round 9
// speedup vs baseline: 1.3176x; 1.1078x over previous
#include <cuda_runtime.h>
#include <math.h>

#define B_  8
#define C_  3
#define H_  512
#define W_  512
#define FR_ 3
#define KS_ 7

#define TILE 32
#define HALO (TILE + 2*FR_)     // 38
#define P2   21                 // row pitch in u64 units (42 floats): conflict-free
#define NT   256
#define NBLOCKS (B_ * (H_/TILE) * (W_/TILE))   // 2048

typedef unsigned long long u64;

__device__ float        g_partials[NBLOCKS];
__device__ unsigned int g_done = 0;   // self-resetting via atomicInc wrap

// ---- f32x2 packed helpers (sm_103a) ----
__device__ __forceinline__ void upk2(u64 v, float& a, float& b) {
    asm("mov.b64 {%0,%1}, %2;" : "=f"(a), "=f"(b) : "l"(v));
}
__device__ __forceinline__ u64 mul2(u64 a, u64 b) {
    u64 r; asm("mul.rn.f32x2 %0,%1,%2;" : "=l"(r) : "l"(a), "l"(b)); return r;
}
__device__ __forceinline__ u64 fma2(u64 a, u64 b, u64 c) {
    u64 r; asm("fma.rn.f32x2 %0,%1,%2,%3;" : "=l"(r) : "l"(a), "l"(b), "l"(c)); return r;
}
__device__ __forceinline__ float ex2f(float x) {
    float r; asm("ex2.approx.ftz.f32 %0,%1;" : "=f"(r) : "f"(x)); return r;
}
__device__ __forceinline__ u64 bc2(float x) {   // compile-time broadcast
    unsigned int u = __float_as_uint(x);
    return ((u64)u << 32) | (u64)u;
}

__device__ __forceinline__ int reflect_idx(int i, int n) {
    if (i < 0) i = -i;
    if (i >= n) i = 2*n - 2 - i;
    return i;
}

#define LOG2A  (-2.65056562f)       // log2(1/sumG^2)
#define GLOG   (-0.72134751f)       // log2 Gaussian coefficient: -d^2 * 0.72134751

__global__ __launch_bounds__(NT, 4)
void blt_loss_kernel(const float* __restrict__ in, float* __restrict__ out)
{
    // tA: tile; tB: tile shifted left one float. All tap pairs -> aligned LDS.64.
    __shared__ u64 tA[C_][HALO][P2];
    __shared__ u64 tB[C_][HALO][P2];
    __shared__ float warp_sums[NT / 32];
    __shared__ int   is_last;

    const int tid = threadIdx.x;
    const int x0b = blockIdx.x * TILE;
    const int y0b = blockIdx.y * TILE;
    const int b   = blockIdx.z;

    // ---- load tile + halo (reflect), write both copies ----
    {
        float* fA = (float*)tA;
        float* fB = (float*)tB;
        const float* base = in + (size_t)b * C_ * H_ * W_;
        for (int idx = tid; idx < C_ * HALO * HALO; idx += NT) {
            int c   = idx / (HALO * HALO);
            int rem = idx - c * (HALO * HALO);
            int iy  = rem / HALO;
            int ix  = rem - iy * HALO;
            int gy  = reflect_idx(y0b - FR_ + iy, H_);
            int gx  = reflect_idx(x0b - FR_ + ix, W_);
            float v = base[(c * H_ + gy) * W_ + gx];
            int off = (c * HALO + iy) * (2 * P2);
            fA[off + ix] = v;
            if (ix > 0) fB[off + ix - 1] = v;
        }
    }
    __syncthreads();

    // Thread -> 4 consecutive x pixels in one row (2 packed pairs)
    const int ty = tid >> 3;            // 0..31
    const int h  = (tid & 7) * 2;       // u64 base index

    const u64 cA0 = tB[0][ty + FR_][h + 1];
    const u64 cA1 = tB[1][ty + FR_][h + 1];
    const u64 cA2 = tB[2][ty + FR_][h + 1];
    const u64 cB0 = tB[0][ty + FR_][h + 2];
    const u64 cB1 = tB[1][ty + FR_][h + 2];
    const u64 cB2 = tB[2][ty + FR_][h + 2];

    const u64 SC2  = bc2(-72.13475204f);   // -50*log2(e)
    const u64 NEG1 = bc2(-1.0f);

    // scalar accumulators (lo/hi lanes, 2 per pair for ILP)
    float aAl0 = 0.f, aAh0 = 0.f, aAl1 = 0.f, aAh1 = 0.f;
    float aBl0 = 0.f, aBh0 = 0.f, aBl1 = 0.f, aBh1 = 0.f;

    // ===== MAIN: 24 positive-half taps, weight 2 folded into lc (+1.0 log2) =====
    #pragma unroll
    for (int k = FR_; k < KS_; k++) {
        const int row = ty + k;
        const int dy  = k - FR_;
        const int l0  = (k == FR_) ? (FR_ + 1) : 0;

        #pragma unroll
        for (int l = 0; l < KS_; l++) {
            if (l < l0) continue;
            const int dx = l - FR_;
            const float lc  = LOG2A + 1.0f + GLOG * (float)(dy*dy + dx*dx);
            const u64   lc2 = bc2(lc);
            const int   j   = l >> 1;

            u64 nA0 = (l & 1) ? tB[0][row][h + j] : tA[0][row][h + j];
            u64 nA1 = (l & 1) ? tB[1][row][h + j] : tA[1][row][h + j];
            u64 nA2 = (l & 1) ? tB[2][row][h + j] : tA[2][row][h + j];
            u64 nB0 = (l & 1) ? tB[0][row][h + j + 1] : tA[0][row][h + j + 1];
            u64 nB1 = (l & 1) ? tB[1][row][h + j + 1] : tA[1][row][h + j + 1];
            u64 nB2 = (l & 1) ? tB[2][row][h + j + 1] : tA[2][row][h + j + 1];

            { // pair A
                u64 d0 = fma2(nA0, NEG1, cA0);
                u64 d1 = fma2(nA1, NEG1, cA1);
                u64 d2 = fma2(nA2, NEG1, cA2);
                u64 s  = fma2(d2, d2, fma2(d1, d1, mul2(d0, d0)));
                u64 t  = fma2(s, SC2, lc2);
                float tl, th;   upk2(t, tl, th);
                float el = ex2f(tl), eh = ex2f(th);
                float d0l,d0h,d1l,d1h,d2l,d2h;
                upk2(d0, d0l, d0h); upk2(d1, d1l, d1h); upk2(d2, d2l, d2h);
                float Ll = fabsf(d0l) + fabsf(d1l) + fabsf(d2l);
                float Lh = fabsf(d0h) + fabsf(d1h) + fabsf(d2h);
                if (l & 1) { aAl1 = fmaf(Ll, el, aAl1); aAh1 = fmaf(Lh, eh, aAh1); }
                else       { aAl0 = fmaf(Ll, el, aAl0); aAh0 = fmaf(Lh, eh, aAh0); }
            }
            { // pair B
                u64 d0 = fma2(nB0, NEG1, cB0);
                u64 d1 = fma2(nB1, NEG1, cB1);
                u64 d2 = fma2(nB2, NEG1, cB2);
                u64 s  = fma2(d2, d2, fma2(d1, d1, mul2(d0, d0)));
                u64 t  = fma2(s, SC2, lc2);
                float tl, th;   upk2(t, tl, th);
                float el = ex2f(tl), eh = ex2f(th);
                float d0l,d0h,d1l,d1h,d2l,d2h;
                upk2(d0, d0l, d0h); upk2(d1, d1l, d1h); upk2(d2, d2l, d2h);
                float Ll = fabsf(d0l) + fabsf(d1l) + fabsf(d2l);
                float Lh = fabsf(d0h) + fabsf(d1h) + fabsf(d2h);
                if (l & 1) { aBl1 = fmaf(Ll, el, aBl1); aBh1 = fmaf(Lh, eh, aBh1); }
                else       { aBl0 = fmaf(Ll, el, aBl0); aBh0 = fmaf(Lh, eh, aBh0); }
            }
        }
    }

    // ===== CORRECTION: only border blocks; exact fix for reflecting taps =====
    if (x0b == 0 || y0b == 0 || x0b == W_ - TILE || y0b == H_ - TILE) {
        const int ys = y0b + ty;
        const int xa = x0b + 2 * h;

        #pragma unroll 1
        for (int dy = -FR_; dy <= FR_; dy++) {
            const int  row = ty + FR_ + dy;
            const bool inY = (unsigned)(ys + dy) < (unsigned)H_;
            #pragma unroll 1
            for (int dx = -FR_; dx <= FR_; dx++) {
                if (dy == 0 && dx == 0) continue;
                const bool in0 = inY && ((unsigned)(xa + dx)     < (unsigned)W_);
                const bool in1 = inY && ((unsigned)(xa + 1 + dx) < (unsigned)W_);
                const bool in2 = inY && ((unsigned)(xa + 2 + dx) < (unsigned)W_);
                const bool in3 = inY && ((unsigned)(xa + 3 + dx) < (unsigned)W_);
                if (in0 & in1 & in2 & in3) continue;

                const bool inH = (dy > 0) || (dy == 0 && dx > 0);
                const float sg = inH ? -1.0f : 1.0f;
                const float m0 = in0 ? 0.0f : sg;
                const float m1 = in1 ? 0.0f : sg;
                const float m2f = in2 ? 0.0f : sg;
                const float m3 = in3 ? 0.0f : sg;

                const float lc  = LOG2A + GLOG * (float)(dy*dy + dx*dx);  // 1x weight
                const u64   lc2 = bc2(lc);

                const int l = dx + FR_;
                const int j = l >> 1;
                u64 nA0, nA1, nA2, nB0, nB1, nB2;
                if (l & 1) {
                    nA0 = tB[0][row][h+j];   nA1 = tB[1][row][h+j];   nA2 = tB[2][row][h+j];
                    nB0 = tB[0][row][h+j+1]; nB1 = tB[1][row][h+j+1]; nB2 = tB[2][row][h+j+1];
                } else {
                    nA0 = tA[0][row][h+j];   nA1 = tA[1][row][h+j];   nA2 = tA[2][row][h+j];
                    nB0 = tA[0][row][h+j+1]; nB1 = tA[1][row][h+j+1]; nB2 = tA[2][row][h+j+1];
                }

                { // pair A
                    u64 d0 = fma2(nA0, NEG1, cA0);
                    u64 d1 = fma2(nA1, NEG1, cA1);
                    u64 d2 = fma2(nA2, NEG1, cA2);
                    u64 s  = fma2(d2, d2, fma2(d1, d1, mul2(d0, d0)));
                    u64 t  = fma2(s, SC2, lc2);
                    float tl, th; upk2(t, tl, th);
                    float el = ex2f(tl), eh = ex2f(th);
                    float d0l,d0h,d1l,d1h,d2l,d2h;
                    upk2(d0, d0l, d0h); upk2(d1, d1l, d1h); upk2(d2, d2l, d2h);
                    float Ll = fabsf(d0l) + fabsf(d1l) + fabsf(d2l);
                    float Lh = fabsf(d0h) + fabsf(d1h) + fabsf(d2h);
                    aAl0 = fmaf(Ll * el, m0, aAl0);
                    aAh0 = fmaf(Lh * eh, m1, aAh0);
                }
                { // pair B
                    u64 d0 = fma2(nB0, NEG1, cB0);
                    u64 d1 = fma2(nB1, NEG1, cB1);
                    u64 d2 = fma2(nB2, NEG1, cB2);
                    u64 s  = fma2(d2, d2, fma2(d1, d1, mul2(d0, d0)));
                    u64 t  = fma2(s, SC2, lc2);
                    float tl, th; upk2(t, tl, th);
                    float el = ex2f(tl), eh = ex2f(th);
                    float d0l,d0h,d1l,d1h,d2l,d2h;
                    upk2(d0, d0l, d0h); upk2(d1, d1l, d1h); upk2(d2, d2l, d2h);
                    float Ll = fabsf(d0l) + fabsf(d1l) + fabsf(d2l);
                    float Lh = fabsf(d0h) + fabsf(d1h) + fabsf(d2h);
                    aBl0 = fmaf(Ll * el, m2f, aBl0);
                    aBh0 = fmaf(Lh * eh, m3, aBh0);
                }
            }
        }
    }

    // ---- reduce: thread -> warp -> block ----
    float acc = ((aAl0 + aAh0) + (aAl1 + aAh1)) + ((aBl0 + aBh0) + (aBl1 + aBh1));

    #pragma unroll
    for (int ofs = 16; ofs > 0; ofs >>= 1)
        acc += __shfl_down_sync(0xffffffffu, acc, ofs);

    if ((tid & 31) == 0) warp_sums[tid >> 5] = acc;
    __syncthreads();

    if (tid == 0) {
        float bs = 0.0f;
        #pragma unroll
        for (int wi = 0; wi < NT / 32; wi++) bs += warp_sums[wi];
        const int bidx = (blockIdx.z * gridDim.y + blockIdx.y) * gridDim.x + blockIdx.x;
        g_partials[bidx] = bs;
        __threadfence();
        unsigned int old = atomicInc(&g_done, NBLOCKS - 1);  // wraps to 0: self-reset
        is_last = (old == NBLOCKS - 1);
    }
    __syncthreads();

    // ---- last block: final deterministic reduce ----
    if (is_last) {
        float s = 0.0f;
        for (int i = tid; i < NBLOCKS; i += NT)
            s += __ldcg(&g_partials[i]);

        #pragma unroll
        for (int ofs = 16; ofs > 0; ofs >>= 1)
            s += __shfl_down_sync(0xffffffffu, s, ofs);

        if ((tid & 31) == 0) warp_sums[tid >> 5] = s;
        __syncthreads();

        if (tid == 0) {
            float total = 0.0f;
            #pragma unroll
            for (int wi = 0; wi < NT / 32; wi++) total += warp_sums[wi];
            out[0] = total * (1.0f / (float)((size_t)B_ * C_ * H_ * W_));
        }
    }
}

extern "C" void kernel_launch(void* const* d_in, const int* in_sizes, int n_in,
                              void* d_out, int out_size)
{
    const float* in = (const float*)d_in[0];
    float* out = (float*)d_out;

    dim3 grid(W_ / TILE, H_ / TILE, B_);   // 16,16,8
    blt_loss_kernel<<<grid, NT>>>(in, out);
}

// round 10
// speedup vs baseline: 1.3607x; 1.0327x over previous
#include <cuda_runtime.h>
#include <math.h>

#define B_  8
#define C_  3
#define H_  512
#define W_  512
#define FR_ 3
#define KS_ 7

#define TILE 32
#define HALO (TILE + 2*FR_)     // 38
#define P2   21                 // row pitch in u64 units (42 floats): conflict-free
#define NT   256
#define NBLOCKS (B_ * (H_/TILE) * (W_/TILE))   // 2048

typedef unsigned long long u64;

__device__ float        g_partials[NBLOCKS];
__device__ unsigned int g_done = 0;   // self-resetting via atomicInc wrap

// ---- f32x2 packed helpers (sm_103a) ----
__device__ __forceinline__ void upk2(u64 v, float& a, float& b) {
    asm("mov.b64 {%0,%1}, %2;" : "=f"(a), "=f"(b) : "l"(v));
}
__device__ __forceinline__ u64 mul2(u64 a, u64 b) {
    u64 r; asm("mul.rn.f32x2 %0,%1,%2;" : "=l"(r) : "l"(a), "l"(b)); return r;
}
__device__ __forceinline__ u64 fma2(u64 a, u64 b, u64 c) {
    u64 r; asm("fma.rn.f32x2 %0,%1,%2,%3;" : "=l"(r) : "l"(a), "l"(b), "l"(c)); return r;
}
__device__ __forceinline__ float ex2f(float x) {
    float r; asm("ex2.approx.ftz.f32 %0,%1;" : "=f"(r) : "f"(x)); return r;
}
__device__ __forceinline__ u64 bc2(float x) {   // compile-time broadcast
    unsigned int u = __float_as_uint(x);
    return ((u64)u << 32) | (u64)u;
}

__device__ __forceinline__ int reflect_idx(int i, int n) {
    if (i < 0) i = -i;
    if (i >= n) i = 2*n - 2 - i;
    return i;
}

#define LOG2A  (-2.65056562f)       // log2(1/sumG^2)
#define GLOG   (-0.72134751f)       // log2 Gaussian coefficient: -d^2 * 0.72134751

__global__ __launch_bounds__(NT, 5)
void blt_loss_kernel(const float* __restrict__ in, float* __restrict__ out)
{
    // tA: tile; tB: tile shifted left one float. All tap pairs -> aligned LDS.64.
    __shared__ u64 tA[C_][HALO][P2];
    __shared__ u64 tB[C_][HALO][P2];
    __shared__ float warp_sums[NT / 32];
    __shared__ int   is_last;

    const int tid = threadIdx.x;
    const int x0b = blockIdx.x * TILE;
    const int y0b = blockIdx.y * TILE;
    const int b   = blockIdx.z;

    // ---- load tile + halo (reflect), write both copies ----
    {
        float* fA = (float*)tA;
        float* fB = (float*)tB;
        const float* base = in + (size_t)b * C_ * H_ * W_;
        for (int idx = tid; idx < C_ * HALO * HALO; idx += NT) {
            int c   = idx / (HALO * HALO);
            int rem = idx - c * (HALO * HALO);
            int iy  = rem / HALO;
            int ix  = rem - iy * HALO;
            int gy  = reflect_idx(y0b - FR_ + iy, H_);
            int gx  = reflect_idx(x0b - FR_ + ix, W_);
            float v = base[(c * H_ + gy) * W_ + gx];
            int off = (c * HALO + iy) * (2 * P2);
            fA[off + ix] = v;
            if (ix > 0) fB[off + ix - 1] = v;
        }
    }
    __syncthreads();

    // Thread -> 4 consecutive x pixels in one row (2 packed pairs)
    const int ty = tid >> 3;            // 0..31
    const int h  = (tid & 7) * 2;       // u64 base index

    const u64 cA0 = tB[0][ty + FR_][h + 1];
    const u64 cA1 = tB[1][ty + FR_][h + 1];
    const u64 cA2 = tB[2][ty + FR_][h + 1];
    const u64 cB0 = tB[0][ty + FR_][h + 2];
    const u64 cB1 = tB[1][ty + FR_][h + 2];
    const u64 cB2 = tB[2][ty + FR_][h + 2];

    const u64 SC2  = bc2(-72.13475204f);   // -50*log2(e)
    const u64 NEG1 = bc2(-1.0f);

    // 4 scalar accumulators (lane x parity); A and B pairs share them.
    float ac_l0 = 0.f, ac_h0 = 0.f, ac_l1 = 0.f, ac_h1 = 0.f;

    // ===== MAIN: 24 positive-half taps, weight 2 folded into lc (+1.0 log2) =====
    #pragma unroll
    for (int k = FR_; k < KS_; k++) {
        const int row = ty + k;
        const int dy  = k - FR_;
        const int l0  = (k == FR_) ? (FR_ + 1) : 0;

        #pragma unroll
        for (int l = 0; l < KS_; l++) {
            if (l < l0) continue;
            const int dx = l - FR_;
            const float lc  = LOG2A + 1.0f + GLOG * (float)(dy*dy + dx*dx);
            const u64   lc2 = bc2(lc);
            const int   j   = l >> 1;

            u64 nA0 = (l & 1) ? tB[0][row][h + j] : tA[0][row][h + j];
            u64 nA1 = (l & 1) ? tB[1][row][h + j] : tA[1][row][h + j];
            u64 nA2 = (l & 1) ? tB[2][row][h + j] : tA[2][row][h + j];
            u64 nB0 = (l & 1) ? tB[0][row][h + j + 1] : tA[0][row][h + j + 1];
            u64 nB1 = (l & 1) ? tB[1][row][h + j + 1] : tA[1][row][h + j + 1];
            u64 nB2 = (l & 1) ? tB[2][row][h + j + 1] : tA[2][row][h + j + 1];

            { // pair A
                u64 d0 = fma2(nA0, NEG1, cA0);
                u64 d1 = fma2(nA1, NEG1, cA1);
                u64 d2 = fma2(nA2, NEG1, cA2);
                u64 s  = fma2(d2, d2, fma2(d1, d1, mul2(d0, d0)));
                u64 t  = fma2(s, SC2, lc2);
                float tl, th;   upk2(t, tl, th);
                float el = ex2f(tl), eh = ex2f(th);
                float d0l,d0h,d1l,d1h,d2l,d2h;
                upk2(d0, d0l, d0h); upk2(d1, d1l, d1h); upk2(d2, d2l, d2h);
                float Ll = fabsf(d0l) + fabsf(d1l) + fabsf(d2l);
                float Lh = fabsf(d0h) + fabsf(d1h) + fabsf(d2h);
                if (l & 1) { ac_l1 = fmaf(Ll, el, ac_l1); ac_h1 = fmaf(Lh, eh, ac_h1); }
                else       { ac_l0 = fmaf(Ll, el, ac_l0); ac_h0 = fmaf(Lh, eh, ac_h0); }
            }
            { // pair B
                u64 d0 = fma2(nB0, NEG1, cB0);
                u64 d1 = fma2(nB1, NEG1, cB1);
                u64 d2 = fma2(nB2, NEG1, cB2);
                u64 s  = fma2(d2, d2, fma2(d1, d1, mul2(d0, d0)));
                u64 t  = fma2(s, SC2, lc2);
                float tl, th;   upk2(t, tl, th);
                float el = ex2f(tl), eh = ex2f(th);
                float d0l,d0h,d1l,d1h,d2l,d2h;
                upk2(d0, d0l, d0h); upk2(d1, d1l, d1h); upk2(d2, d2l, d2h);
                float Ll = fabsf(d0l) + fabsf(d1l) + fabsf(d2l);
                float Lh = fabsf(d0h) + fabsf(d1h) + fabsf(d2h);
                if (l & 1) { ac_l1 = fmaf(Ll, el, ac_l1); ac_h1 = fmaf(Lh, eh, ac_h1); }
                else       { ac_l0 = fmaf(Ll, el, ac_l0); ac_h0 = fmaf(Lh, eh, ac_h0); }
            }
        }
    }

    // ===== CORRECTION: only border blocks; exact fix for reflecting taps =====
    if (x0b == 0 || y0b == 0 || x0b == W_ - TILE || y0b == H_ - TILE) {
        const int ys = y0b + ty;
        const int xa = x0b + 2 * h;

        #pragma unroll 1
        for (int dy = -FR_; dy <= FR_; dy++) {
            const int  row = ty + FR_ + dy;
            const bool inY = (unsigned)(ys + dy) < (unsigned)H_;
            #pragma unroll 1
            for (int dx = -FR_; dx <= FR_; dx++) {
                if (dy == 0 && dx == 0) continue;
                const bool in0 = inY && ((unsigned)(xa + dx)     < (unsigned)W_);
                const bool in1 = inY && ((unsigned)(xa + 1 + dx) < (unsigned)W_);
                const bool in2 = inY && ((unsigned)(xa + 2 + dx) < (unsigned)W_);
                const bool in3 = inY && ((unsigned)(xa + 3 + dx) < (unsigned)W_);
                if (in0 & in1 & in2 & in3) continue;

                const bool inH = (dy > 0) || (dy == 0 && dx > 0);
                const float sg = inH ? -1.0f : 1.0f;
                const float m0 = in0 ? 0.0f : sg;
                const float m1 = in1 ? 0.0f : sg;
                const float m2f = in2 ? 0.0f : sg;
                const float m3 = in3 ? 0.0f : sg;

                const float lc  = LOG2A + GLOG * (float)(dy*dy + dx*dx);  // 1x weight
                const u64   lc2 = bc2(lc);

                const int l = dx + FR_;
                const int j = l >> 1;
                u64 nA0, nA1, nA2, nB0, nB1, nB2;
                if (l & 1) {
                    nA0 = tB[0][row][h+j];   nA1 = tB[1][row][h+j];   nA2 = tB[2][row][h+j];
                    nB0 = tB[0][row][h+j+1]; nB1 = tB[1][row][h+j+1]; nB2 = tB[2][row][h+j+1];
                } else {
                    nA0 = tA[0][row][h+j];   nA1 = tA[1][row][h+j];   nA2 = tA[2][row][h+j];
                    nB0 = tA[0][row][h+j+1]; nB1 = tA[1][row][h+j+1]; nB2 = tA[2][row][h+j+1];
                }

                { // pair A
                    u64 d0 = fma2(nA0, NEG1, cA0);
                    u64 d1 = fma2(nA1, NEG1, cA1);
                    u64 d2 = fma2(nA2, NEG1, cA2);
                    u64 s  = fma2(d2, d2, fma2(d1, d1, mul2(d0, d0)));
                    u64 t  = fma2(s, SC2, lc2);
                    float tl, th; upk2(t, tl, th);
                    float el = ex2f(tl), eh = ex2f(th);
                    float d0l,d0h,d1l,d1h,d2l,d2h;
                    upk2(d0, d0l, d0h); upk2(d1, d1l, d1h); upk2(d2, d2l, d2h);
                    float Ll = fabsf(d0l) + fabsf(d1l) + fabsf(d2l);
                    float Lh = fabsf(d0h) + fabsf(d1h) + fabsf(d2h);
                    ac_l0 = fmaf(Ll * el, m0, ac_l0);
                    ac_h0 = fmaf(Lh * eh, m1, ac_h0);
                }
                { // pair B
                    u64 d0 = fma2(nB0, NEG1, cB0);
                    u64 d1 = fma2(nB1, NEG1, cB1);
                    u64 d2 = fma2(nB2, NEG1, cB2);
                    u64 s  = fma2(d2, d2, fma2(d1, d1, mul2(d0, d0)));
                    u64 t  = fma2(s, SC2, lc2);
                    float tl, th; upk2(t, tl, th);
                    float el = ex2f(tl), eh = ex2f(th);
                    float d0l,d0h,d1l,d1h,d2l,d2h;
                    upk2(d0, d0l, d0h); upk2(d1, d1l, d1h); upk2(d2, d2l, d2h);
                    float Ll = fabsf(d0l) + fabsf(d1l) + fabsf(d2l);
                    float Lh = fabsf(d0h) + fabsf(d1h) + fabsf(d2h);
                    ac_l1 = fmaf(Ll * el, m2f, ac_l1);
                    ac_h1 = fmaf(Lh * eh, m3, ac_h1);
                }
            }
        }
    }

    // ---- reduce: thread -> warp -> block ----
    float acc = (ac_l0 + ac_h0) + (ac_l1 + ac_h1);

    #pragma unroll
    for (int ofs = 16; ofs > 0; ofs >>= 1)
        acc += __shfl_down_sync(0xffffffffu, acc, ofs);

    if ((tid & 31) == 0) warp_sums[tid >> 5] = acc;
    __syncthreads();

    if (tid == 0) {
        float bs = 0.0f;
        #pragma unroll
        for (int wi = 0; wi < NT / 32; wi++) bs += warp_sums[wi];
        const int bidx = (blockIdx.z * gridDim.y + blockIdx.y) * gridDim.x + blockIdx.x;
        g_partials[bidx] = bs;
        __threadfence();
        unsigned int old = atomicInc(&g_done, NBLOCKS - 1);  // wraps to 0: self-reset
        is_last = (old == NBLOCKS - 1);
    }
    __syncthreads();

    // ---- last block: final deterministic reduce ----
    if (is_last) {
        float s = 0.0f;
        for (int i = tid; i < NBLOCKS; i += NT)
            s += __ldcg(&g_partials[i]);

        #pragma unroll
        for (int ofs = 16; ofs > 0; ofs >>= 1)
            s += __shfl_down_sync(0xffffffffu, s, ofs);

        if ((tid & 31) == 0) warp_sums[tid >> 5] = s;
        __syncthreads();

        if (tid == 0) {
            float total = 0.0f;
            #pragma unroll
            for (int wi = 0; wi < NT / 32; wi++) total += warp_sums[wi];
            out[0] = total * (1.0f / (float)((size_t)B_ * C_ * H_ * W_));
        }
    }
}

extern "C" void kernel_launch(void* const* d_in, const int* in_sizes, int n_in,
                              void* d_out, int out_size)
{
    const float* in = (const float*)d_in[0];
    float* out = (float*)d_out;

    dim3 grid(W_ / TILE, H_ / TILE, B_);   // 16,16,8
    blt_loss_kernel<<<grid, NT>>>(in, out);
}